// round 16
// baseline (speedup 1.0000x reference)
#include <cuda_runtime.h>
#include <cuda_fp16.h>
#include <stdint.h>

// Problem constants
#define NPLANES 32            // B*C = 2*16
#define NTEX    512
#define HT      64
#define WT      64
#define TEXELS  (NTEX*HT*WT)  // 2,097,152 texels; plane stride in x
#define HO      1024
#define WO      1024
#define NPIX    (HO*WO)

#define TILE_T  256           // texels per transpose tile
#define TILES_PER_BLOCK 4

// 128 MB transposed fp16 atlas: g_xt_h[texel][channel]; one texel's 32
// channels = one 64B half-line (4 x 16B channel quads).
__device__ __half g_xt_h[(size_t)TEXELS * NPLANES];

// Phase B helper: warp w covers texels [w*8, w*8+8) of the tile.
__device__ __forceinline__ void transpose_phaseB(const float (*tile)[TILE_T + 1],
                                                 int w, int lane, int tbase) {
    const int tq = lane >> 2;          // 0..7 texel within warp's group
    const int c  = lane & 3;           // 0..3 channel oct
    const int t  = w * 8 + tq;

    float v[8];
    #pragma unroll
    for (int k = 0; k < 8; k++) v[k] = tile[8 * c + k][t];

    uint4 pk;
    { const __half2 h = __floats2half2_rn(v[0], v[1]); pk.x = *(const unsigned int*)&h; }
    { const __half2 h = __floats2half2_rn(v[2], v[3]); pk.y = *(const unsigned int*)&h; }
    { const __half2 h = __floats2half2_rn(v[4], v[5]); pk.z = *(const unsigned int*)&h; }
    { const __half2 h = __floats2half2_rn(v[6], v[7]); pk.w = *(const unsigned int*)&h; }
    *(uint4*)(g_xt_h + (size_t)(tbase + t) * NPLANES + 8 * c) = pk;
}

__device__ __forceinline__ void sts_tile(float (*tile)[TILE_T + 1],
                                         int w, int lane,
                                         const float4 a, const float4 b) {
    const int t0 = lane * 4;
    tile[w][t0 + 0] = a.x; tile[w][t0 + 1] = a.y;
    tile[w][t0 + 2] = a.z; tile[w][t0 + 3] = a.w;
    const int t1 = (32 + lane) * 4;
    tile[w][t1 + 0] = b.x; tile[w][t1 + 1] = b.y;
    tile[w][t1 + 2] = b.z; tile[w][t1 + 3] = b.w;
}

// ---------------------------------------------------------------------------
// Pass 1: transpose + fp32->fp16, FOUR pipelined 32x256 tiles per block:
// tile i+1's LDG.128s are in flight during tile i's phase B + barriers.
// ---------------------------------------------------------------------------
__global__ __launch_bounds__(1024) void transpose_kernel(const float* __restrict__ x) {
    __shared__ float tile[32][TILE_T + 1];   // pitch 257 -> bank (r+t)%32
    const int w    = threadIdx.x >> 5;
    const int lane = threadIdx.x & 31;
    const int tbase0 = blockIdx.x * (TILES_PER_BLOCK * TILE_T);

    const float4* src = (const float4*)(x + (size_t)w * TEXELS + tbase0);

    float4 a = src[lane];
    float4 b = src[32 + lane];
    sts_tile(tile, w, lane, a, b);
    __syncthreads();

    #pragma unroll
    for (int i = 0; i < TILES_PER_BLOCK; i++) {
        float4 a2, b2;
        if (i < TILES_PER_BLOCK - 1) {          // prefetch next tile
            a2 = src[(i + 1) * 64 + lane];
            b2 = src[(i + 1) * 64 + 32 + lane];
        }
        transpose_phaseB(tile, w, lane, tbase0 + i * TILE_T);
        if (i < TILES_PER_BLOCK - 1) {
            __syncthreads();                    // phase B reads done
            sts_tile(tile, w, lane, a2, b2);
            __syncthreads();                    // tile refilled
        }
    }

#if __CUDA_ARCH__ >= 900
    cudaTriggerProgrammaticLaunchCompletion();
#endif
}

// ---------------------------------------------------------------------------
// Pass 2: 2 pixels per thread (block of 256 -> 128 pixels), 4 lanes per
// pixel, LDG.128 corner gathers (8 independent 128-bit loads per thread).
// __stcs coalesced output; PDL gate on atlas reads.
// ---------------------------------------------------------------------------
__global__ __launch_bounds__(256) void sample_kernel(
    const int*    __restrict__ qidx,
    const float2* __restrict__ uv,
    float*        __restrict__ out) {

    __shared__ float s[128][33];
    const int tid  = threadIdx.x;
    const int w    = tid >> 5;
    const int lane = tid & 31;
    const int p    = lane >> 2;        // pixel slot within warp 0..7
    const int c    = lane & 3;         // channel quad 0..3
    const int pixbase = blockIdx.x * 128;

    const uint4* atlas4 = (const uint4*)g_xt_h;

    // Two pixels per thread: pl and pl+64.
    int   pl[2];
    pl[0] = w * 8 + p;
    pl[1] = pl[0] + 64;

    int    rn[2];
    float2 tuv[2];
    #pragma unroll
    for (int q = 0; q < 2; q++) {
        rn[q]  = __ldcs(&qidx[pixbase + pl[q]]);
        tuv[q] = __ldcs(&uv[pixbase + pl[q]]);
    }

    int   l00[2], l01[2], l10[2], l11[2];
    float wuv[2][2];
    #pragma unroll
    for (int q = 0; q < 2; q++) {
        const int n = min(max(rn[q], 0), NTEX - 1);
        const float u   = tuv[q].x * 63.0f;
        const float v   = tuv[q].y * 63.0f;
        const float x0f = floorf(u);
        const float y0f = floorf(v);
        wuv[q][0] = u - x0f;
        wuv[q][1] = v - y0f;

        int x0 = (int)x0f; x0 = min(max(x0, 0), WT - 1);
        int y0 = (int)y0f; y0 = min(max(y0, 0), HT - 1);
        const int x1 = min(x0 + 1, WT - 1);
        const int y1 = min(y0 + 1, HT - 1);
        const int rb = n * (HT * WT);
        const int r0 = rb + y0 * WT;
        const int r1 = rb + y1 * WT;
        l00[q] = r0 + x0; l01[q] = r0 + x1;
        l10[q] = r1 + x0; l11[q] = r1 + x1;
    }

#if __CUDA_ARCH__ >= 900
    cudaGridDependencySynchronize();   // wait for transpose's atlas stores
#endif

    #pragma unroll
    for (int q = 0; q < 2; q++) {
        const uint4 q00 = atlas4[(size_t)l00[q] * 4 + c];
        const uint4 q01 = atlas4[(size_t)l01[q] * 4 + c];
        const uint4 q10 = atlas4[(size_t)l10[q] * 4 + c];
        const uint4 q11 = atlas4[(size_t)l11[q] * 4 + c];

        const unsigned int* a00 = (const unsigned int*)&q00;
        const unsigned int* a01 = (const unsigned int*)&q01;
        const unsigned int* a10 = (const unsigned int*)&q10;
        const unsigned int* a11 = (const unsigned int*)&q11;

        const float wu = wuv[q][0];
        const float wv = wuv[q][1];

        #pragma unroll
        for (int k = 0; k < 4; k++) {
            const float2 g00 = __half22float2(*(const __half2*)&a00[k]);
            const float2 g01 = __half22float2(*(const __half2*)&a01[k]);
            const float2 g10 = __half22float2(*(const __half2*)&a10[k]);
            const float2 g11 = __half22float2(*(const __half2*)&a11[k]);

            const float topx = fmaf(wu, g01.x - g00.x, g00.x);
            const float botx = fmaf(wu, g11.x - g10.x, g10.x);
            const float topy = fmaf(wu, g01.y - g00.y, g00.y);
            const float boty = fmaf(wu, g11.y - g10.y, g10.y);

            s[pl[q]][8 * c + 2 * k]     = fmaf(wv, botx - topx, topx);
            s[pl[q]][8 * c + 2 * k + 1] = fmaf(wv, boty - topy, topy);
        }
    }

    __syncthreads();

    // Output: 4 planes per warp, 128 contiguous pixels per plane.
    #pragma unroll
    for (int jj = 0; jj < 4; jj++) {
        const int pp = w * 4 + jj;
        float* o = out + (size_t)pp * NPIX + pixbase;
        __stcs(&o[lane],       s[lane][pp]);
        __stcs(&o[32 + lane],  s[32 + lane][pp]);
        __stcs(&o[64 + lane],  s[64 + lane][pp]);
        __stcs(&o[96 + lane],  s[96 + lane][pp]);
    }
}

extern "C" void kernel_launch(void* const* d_in, const int* in_sizes, int n_in,
                              void* d_out, int out_size) {
    const float*  x    = (const float*)d_in[0];
    const int*    qidx = (const int*)d_in[1];
    const float2* uv   = (const float2*)d_in[2];
    float*        out  = (float*)d_out;

    transpose_kernel<<<TEXELS / (TILES_PER_BLOCK * TILE_T), 1024>>>(x);

    cudaLaunchConfig_t cfg = {};
    cfg.gridDim  = dim3(NPIX / 128);
    cfg.blockDim = dim3(256);
    cudaLaunchAttribute attr[1];
    attr[0].id = cudaLaunchAttributeProgrammaticStreamSerialization;
    attr[0].val.programmaticStreamSerializationAllowed = 1;
    cfg.attrs    = attr;
    cfg.numAttrs = 1;
    cudaError_t err = cudaLaunchKernelEx(&cfg, sample_kernel, qidx, uv, out);
    if (err != cudaSuccess) {
        sample_kernel<<<NPIX / 128, 256>>>(qidx, uv, out);
    }
}

// round 17
// speedup vs baseline: 1.0331x; 1.0331x over previous
#include <cuda_runtime.h>
#include <cuda_fp16.h>
#include <stdint.h>

// Problem constants
#define NPLANES 32            // B*C = 2*16
#define NTEX    512
#define HT      64
#define WT      64
#define TEXELS  (NTEX*HT*WT)  // 2,097,152 texels; plane stride in x
#define HO      1024
#define WO      1024
#define NPIX    (HO*WO)

#define TILE_T  256           // texels per transpose tile (2 tiles per block)

// 128 MB transposed fp16 atlas: g_xt_h[texel][channel]; one texel's 32
// channels = one 64B half-line (4 x 16B channel quads).
__device__ __half g_xt_h[(size_t)TEXELS * NPLANES];

// Phase B helper: warp w covers texels [w*8, w*8+8) of the tile.
// lane = (tq, c): 8 conflict-free LDS.32 (banks (8c+k+t)%32) -> one STG.128.
__device__ __forceinline__ void transpose_phaseB(const float (*tile)[TILE_T + 1],
                                                 int w, int lane, int tbase) {
    const int tq = lane >> 2;          // 0..7 texel within warp's group
    const int c  = lane & 3;           // 0..3 channel oct
    const int t  = w * 8 + tq;

    float v[8];
    #pragma unroll
    for (int k = 0; k < 8; k++) v[k] = tile[8 * c + k][t];

    uint4 pk;
    { const __half2 h = __floats2half2_rn(v[0], v[1]); pk.x = *(const unsigned int*)&h; }
    { const __half2 h = __floats2half2_rn(v[2], v[3]); pk.y = *(const unsigned int*)&h; }
    { const __half2 h = __floats2half2_rn(v[4], v[5]); pk.z = *(const unsigned int*)&h; }
    { const __half2 h = __floats2half2_rn(v[6], v[7]); pk.w = *(const unsigned int*)&h; }
    *(uint4*)(g_xt_h + (size_t)(tbase + t) * NPLANES + 8 * c) = pk;
}

__device__ __forceinline__ void sts_tile(float (*tile)[TILE_T + 1],
                                         int w, int lane,
                                         const float4 a, const float4 b) {
    const int t0 = lane * 4;
    tile[w][t0 + 0] = a.x; tile[w][t0 + 1] = a.y;
    tile[w][t0 + 2] = a.z; tile[w][t0 + 3] = a.w;
    const int t1 = (32 + lane) * 4;
    tile[w][t1 + 0] = b.x; tile[w][t1 + 1] = b.y;
    tile[w][t1 + 2] = b.z; tile[w][t1 + 3] = b.w;
}

// ---------------------------------------------------------------------------
// Pass 1 (R15, best measured): transpose + fp32->fp16, TWO pipelined 32x256
// tiles per block; tile1's LDG.128s in flight during tile0's phase B.
// ---------------------------------------------------------------------------
__global__ __launch_bounds__(1024) void transpose_kernel(const float* __restrict__ x) {
    __shared__ float tile[32][TILE_T + 1];   // pitch 257 -> bank (r+t)%32
    const int w    = threadIdx.x >> 5;
    const int lane = threadIdx.x & 31;
    const int tbase0 = blockIdx.x * (2 * TILE_T);

    const float4* src0 = (const float4*)(x + (size_t)w * TEXELS + tbase0);

    const float4 a0 = src0[lane];
    const float4 b0 = src0[32 + lane];
    sts_tile(tile, w, lane, a0, b0);
    __syncthreads();

    const float4 a1 = src0[64 + lane];   // prefetch tile 1
    const float4 b1 = src0[96 + lane];

    transpose_phaseB(tile, w, lane, tbase0);
    __syncthreads();

    sts_tile(tile, w, lane, a1, b1);
    __syncthreads();

    transpose_phaseB(tile, w, lane, tbase0 + TILE_T);

#if __CUDA_ARCH__ >= 900
    cudaTriggerProgrammaticLaunchCompletion();
#endif
}

// ---------------------------------------------------------------------------
// Pass 2: R14/R15 mapping (1 pixel per thread, 4 lanes per pixel, LDG.128
// corner gathers) but 512-thread blocks covering 128 pixels: same per-thread
// resources and occupancy, half the blocks, wider store phase (each warp
// writes 2 full planes x 128 contiguous pixels).
// ---------------------------------------------------------------------------
__global__ __launch_bounds__(512) void sample_kernel(
    const int*    __restrict__ qidx,
    const float2* __restrict__ uv,
    float*        __restrict__ out) {

    __shared__ float s[128][33];
    const int tid  = threadIdx.x;
    const int w    = tid >> 5;         // warp 0..15
    const int lane = tid & 31;
    const int p    = lane >> 2;        // pixel within warp 0..7
    const int c    = lane & 3;         // channel quad 0..3
    const int pixbase = blockIdx.x * 128;
    const int pl   = w * 8 + p;        // local pixel 0..127
    const int pix  = pixbase + pl;

    const int    rn = __ldcs(&qidx[pix]);
    const float2 t  = __ldcs(&uv[pix]);

    const int n = min(max(rn, 0), NTEX - 1);
    const float u   = t.x * 63.0f;
    const float v   = t.y * 63.0f;
    const float x0f = floorf(u);
    const float y0f = floorf(v);
    const float wu  = u - x0f;
    const float wv  = v - y0f;

    int x0 = (int)x0f; x0 = min(max(x0, 0), WT - 1);
    int y0 = (int)y0f; y0 = min(max(y0, 0), HT - 1);
    const int x1 = min(x0 + 1, WT - 1);
    const int y1 = min(y0 + 1, HT - 1);

    const int rb = n * (HT * WT);
    const int r0 = rb + y0 * WT;
    const int r1 = rb + y1 * WT;

#if __CUDA_ARCH__ >= 900
    cudaGridDependencySynchronize();   // wait for transpose's atlas stores
#endif

    const uint4* atlas4 = (const uint4*)g_xt_h;
    const uint4 q00 = atlas4[(size_t)(r0 + x0) * 4 + c];
    const uint4 q01 = atlas4[(size_t)(r0 + x1) * 4 + c];
    const uint4 q10 = atlas4[(size_t)(r1 + x0) * 4 + c];
    const uint4 q11 = atlas4[(size_t)(r1 + x1) * 4 + c];

    const unsigned int* a00 = (const unsigned int*)&q00;
    const unsigned int* a01 = (const unsigned int*)&q01;
    const unsigned int* a10 = (const unsigned int*)&q10;
    const unsigned int* a11 = (const unsigned int*)&q11;

    #pragma unroll
    for (int k = 0; k < 4; k++) {
        const float2 g00 = __half22float2(*(const __half2*)&a00[k]);
        const float2 g01 = __half22float2(*(const __half2*)&a01[k]);
        const float2 g10 = __half22float2(*(const __half2*)&a10[k]);
        const float2 g11 = __half22float2(*(const __half2*)&a11[k]);

        const float topx = fmaf(wu, g01.x - g00.x, g00.x);
        const float botx = fmaf(wu, g11.x - g10.x, g10.x);
        const float topy = fmaf(wu, g01.y - g00.y, g00.y);
        const float boty = fmaf(wu, g11.y - g10.y, g10.y);

        s[pl][8 * c + 2 * k]     = fmaf(wv, botx - topx, topx);
        s[pl][8 * c + 2 * k + 1] = fmaf(wv, boty - topy, topy);
    }

    __syncthreads();

    // Output: 32 planes / 16 warps = 2 planes per warp; 128 px per plane.
    #pragma unroll
    for (int jj = 0; jj < 2; jj++) {
        const int pp = w * 2 + jj;
        float* o = out + (size_t)pp * NPIX + pixbase;
        __stcs(&o[lane],      s[lane][pp]);
        __stcs(&o[32 + lane], s[32 + lane][pp]);
        __stcs(&o[64 + lane], s[64 + lane][pp]);
        __stcs(&o[96 + lane], s[96 + lane][pp]);
    }
}

extern "C" void kernel_launch(void* const* d_in, const int* in_sizes, int n_in,
                              void* d_out, int out_size) {
    const float*  x    = (const float*)d_in[0];
    const int*    qidx = (const int*)d_in[1];
    const float2* uv   = (const float2*)d_in[2];
    float*        out  = (float*)d_out;

    transpose_kernel<<<TEXELS / (2 * TILE_T), 1024>>>(x);

    cudaLaunchConfig_t cfg = {};
    cfg.gridDim  = dim3(NPIX / 128);
    cfg.blockDim = dim3(512);
    cudaLaunchAttribute attr[1];
    attr[0].id = cudaLaunchAttributeProgrammaticStreamSerialization;
    attr[0].val.programmaticStreamSerializationAllowed = 1;
    cfg.attrs    = attr;
    cfg.numAttrs = 1;
    cudaError_t err = cudaLaunchKernelEx(&cfg, sample_kernel, qidx, uv, out);
    if (err != cudaSuccess) {
        sample_kernel<<<NPIX / 128, 512>>>(qidx, uv, out);
    }
}